// round 1
// baseline (speedup 1.0000x reference)
#include <cuda_runtime.h>
#include <cstdint>

#define Bn 4096
#define Tn 5
#define Vn 8192
#define En 32
#define Hn 512
#define On 1024

// ---------------- scratch (device globals; no allocation allowed) ----------
__device__ __align__(16) float d_X[Tn * Bn * En];   // X[t][b][e]; slot t holds GRU input x_t (t>=1)
__device__ __align__(16) float d_ln0[En];           // LN(init_emb) = x_0 (batch-invariant)
__device__ __align__(16) float d_hA[Bn * Hn];
__device__ __align__(16) float d_hB[Bn * Hn];
__device__ __align__(16) float d_hln[Bn * Hn];

// ---------------- helpers ---------------------------------------------------
__device__ __forceinline__ uint32_t f2tf(float x) {
    uint32_t r; asm volatile("cvt.rna.tf32.f32 %0, %1;" : "=r"(r) : "f"(x)); return r;
}
__device__ __forceinline__ void st_tf32(uint32_t* p, float4 v) {
    p[0] = f2tf(v.x); p[1] = f2tf(v.y); p[2] = f2tf(v.z); p[3] = f2tf(v.w);
}
__device__ __forceinline__ void mma8(float c[4], uint32_t a0, uint32_t a1, uint32_t a2,
                                     uint32_t a3, uint32_t b0, uint32_t b1) {
    asm volatile(
        "mma.sync.aligned.m16n8k8.row.col.f32.tf32.tf32.f32 "
        "{%0,%1,%2,%3}, {%4,%5,%6,%7}, {%8,%9}, {%0,%1,%2,%3};"
        : "+f"(c[0]), "+f"(c[1]), "+f"(c[2]), "+f"(c[3])
        : "r"(a0), "r"(a1), "r"(a2), "r"(a3), "r"(b0), "r"(b1));
}
__device__ __forceinline__ float sigm(float x) { return 1.f / (1.f + __expf(-x)); }
__device__ __forceinline__ float tanh_fast(float x) { return 1.f - 2.f / (1.f + __expf(2.f * x)); }

// ---------------- tiny kernels ----------------------------------------------
__global__ void ln0_kernel(const float* __restrict__ init_emb,
                           const float* __restrict__ g, const float* __restrict__ b) {
    int l = threadIdx.x;  // 32 threads
    float v = init_emb[l];
    float s = v, sq = v * v;
    #pragma unroll
    for (int o = 16; o; o >>= 1) {
        s += __shfl_xor_sync(~0u, s, o);
        sq += __shfl_xor_sync(~0u, sq, o);
    }
    float m = s / 32.f, var = sq / 32.f - m * m;
    float rs = rsqrtf(var + 1e-5f);
    d_ln0[l] = (v - m) * rs * g[l] + b[l];
}

__global__ void zero_kernel() {
    int i = blockIdx.x * blockDim.x + threadIdx.x;
    ((float4*)d_hA)[i] = make_float4(0.f, 0.f, 0.f, 0.f);
}

// ---------------- embedding GEMM + LayerNorm ---------------------------------
// M = B*4 rows (m = b*4 + t, t in 0..3), N = 32, K = 8192. tf32 mma.
// BM=32, BK=64, blockDim=64 (2 warps; each warp 16m x 32n), reg double-buffer.
__global__ void __launch_bounds__(64) embed_kernel(
    const float* __restrict__ msg, const float* __restrict__ W,
    const float* __restrict__ eb, const float* __restrict__ gw, const float* __restrict__ bw) {
    __shared__ uint32_t As[32][68];
    __shared__ uint32_t Bs[32][68];
    const int tid = threadIdx.x;
    const int warp = tid >> 5, lane = tid & 31;
    const int gq = lane >> 2, tq = lane & 3;
    const int m0 = blockIdx.x * 32;
    const int c4 = tid & 15;   // 0..15 (col group of 4 floats)
    const int r0 = tid >> 4;   // 0..3

    const float* aptr[8];
    const float* bptr[8];
    #pragma unroll
    for (int i = 0; i < 8; i++) {
        int m = m0 + r0 + i * 4;
        int bb = m >> 2, tt = m & 3;
        aptr[i] = msg + ((size_t)bb * Tn + tt) * Vn + c4 * 4;
        bptr[i] = W + (size_t)(r0 + i * 4) * Vn + c4 * 4;
    }

    float4 pa[8], pb[8];
    auto LOAD = [&](int it) {
        int k0 = it * 64;
        #pragma unroll
        for (int i = 0; i < 8; i++) pa[i] = *(const float4*)(aptr[i] + k0);
        #pragma unroll
        for (int i = 0; i < 8; i++) pb[i] = *(const float4*)(bptr[i] + k0);
    };
    auto STORE = [&]() {
        #pragma unroll
        for (int i = 0; i < 8; i++) st_tf32(&As[r0 + i * 4][c4 * 4], pa[i]);
        #pragma unroll
        for (int i = 0; i < 8; i++) st_tf32(&Bs[r0 + i * 4][c4 * 4], pb[i]);
    };

    float acc[4][4] = {};
    const int mo = warp * 16;

    LOAD(0); STORE(); __syncthreads();
    const int NIT = Vn / 64;
    for (int it = 0; it < NIT; ++it) {
        if (it + 1 < NIT) LOAD(it + 1);
        #pragma unroll
        for (int kk = 0; kk < 8; kk++) {
            uint32_t a0 = As[mo + gq][kk * 8 + tq];
            uint32_t a1 = As[mo + gq + 8][kk * 8 + tq];
            uint32_t a2 = As[mo + gq][kk * 8 + tq + 4];
            uint32_t a3 = As[mo + gq + 8][kk * 8 + tq + 4];
            #pragma unroll
            for (int nb = 0; nb < 4; nb++) {
                uint32_t b0 = Bs[nb * 8 + gq][kk * 8 + tq];
                uint32_t b1 = Bs[nb * 8 + gq][kk * 8 + tq + 4];
                mma8(acc[nb], a0, a1, a2, a3, b0, b1);
            }
        }
        __syncthreads();
        if (it + 1 < NIT) { STORE(); __syncthreads(); }
    }

    // Epilogue: LayerNorm over the 32 embedding dims (quad holds full row).
    float v0[8], v1[8];
    int col[8];
    #pragma unroll
    for (int nb = 0; nb < 4; nb++) {
        col[nb * 2] = nb * 8 + 2 * tq;
        col[nb * 2 + 1] = nb * 8 + 2 * tq + 1;
        float e0 = eb[col[nb * 2]], e1 = eb[col[nb * 2 + 1]];
        v0[nb * 2] = acc[nb][0] + e0; v0[nb * 2 + 1] = acc[nb][1] + e1;
        v1[nb * 2] = acc[nb][2] + e0; v1[nb * 2 + 1] = acc[nb][3] + e1;
    }
    auto LNROW = [&](float* v, int mrow) {
        float s = 0.f, sq = 0.f;
        #pragma unroll
        for (int i = 0; i < 8; i++) { s += v[i]; sq += v[i] * v[i]; }
        s += __shfl_xor_sync(~0u, s, 1); sq += __shfl_xor_sync(~0u, sq, 1);
        s += __shfl_xor_sync(~0u, s, 2); sq += __shfl_xor_sync(~0u, sq, 2);
        float m = s / 32.f, var = sq / 32.f - m * m;
        float rs = rsqrtf(var + 1e-5f);
        int bb = mrow >> 2, tt = mrow & 3;
        float* xp = d_X + ((size_t)(tt + 1) * Bn + bb) * En;
        #pragma unroll
        for (int i = 0; i < 8; i++)
            xp[col[i]] = (v[i] - m) * rs * gw[col[i]] + bw[col[i]];
    };
    LNROW(v0, m0 + mo + gq);
    LNROW(v1, m0 + mo + gq + 8);
}

// ---------------- GRU step: fused [x|h] @ [Wih|Whh]^T + gates ----------------
// M=4096(b), N=512(H cols), 3 gate tiles per block. K=544 (it 0 = x slice).
__global__ void __launch_bounds__(256) gru_kernel(
    const float* __restrict__ Wih, const float* __restrict__ Whh,
    const float* __restrict__ bih, const float* __restrict__ bhh, int t) {
    __shared__ uint32_t As[64][36];
    __shared__ uint32_t Bs[3][64][36];
    const float* hold = (t & 1) ? d_hB : d_hA;
    float* hnew = (t & 1) ? d_hA : d_hB;

    const int tid = threadIdx.x;
    const int warp = tid >> 5, lane = tid & 31;
    const int gq = lane >> 2, tq = lane & 3;
    const int n0 = blockIdx.x * 64, m0 = blockIdx.y * 64;
    const int mo = (warp & 3) * 16, no = (warp >> 2) * 32;

    float accr[4][4] = {}, accz[4][4] = {}, accnx[4][4] = {}, accnh[4][4] = {};

    for (int it = 0; it < 17; ++it) {
        int k0 = it * 32;
        // A tile: 64 x 32 (x_t for it==0, else h)
        #pragma unroll
        for (int j = 0; j < 2; j++) {
            int lin = tid + j * 256;
            int r = lin >> 3, cc = lin & 7;
            float4 v;
            if (it == 0) {
                if (t == 0) v = *(const float4*)(d_ln0 + cc * 4);
                else        v = *(const float4*)(d_X + ((size_t)t * Bn + m0 + r) * En + cc * 4);
            } else {
                v = *(const float4*)(hold + (size_t)(m0 + r) * Hn + (k0 - 32) + cc * 4);
            }
            st_tf32(&As[r][cc * 4], v);
        }
        // B tiles: 3 gates x 64 x 32
        #pragma unroll
        for (int j = 0; j < 6; j++) {
            int lin = tid + j * 256;
            int gt = lin >> 9, rem = lin & 511, nl = rem >> 3, cc = rem & 7;
            int row = gt * Hn + n0 + nl;
            float4 v = (it == 0)
                ? *(const float4*)(Wih + (size_t)row * En + cc * 4)
                : *(const float4*)(Whh + (size_t)row * Hn + (k0 - 32) + cc * 4);
            st_tf32(&Bs[gt][nl][cc * 4], v);
        }
        __syncthreads();

        float (*accn)[4] = (it == 0) ? accnx : accnh;
        #pragma unroll
        for (int kk = 0; kk < 4; kk++) {
            uint32_t a0 = As[mo + gq][kk * 8 + tq];
            uint32_t a1 = As[mo + gq + 8][kk * 8 + tq];
            uint32_t a2 = As[mo + gq][kk * 8 + tq + 4];
            uint32_t a3 = As[mo + gq + 8][kk * 8 + tq + 4];
            #pragma unroll
            for (int nb = 0; nb < 4; nb++) {
                int nn = no + nb * 8 + gq;
                uint32_t b0 = Bs[0][nn][kk * 8 + tq], b1 = Bs[0][nn][kk * 8 + tq + 4];
                mma8(accr[nb], a0, a1, a2, a3, b0, b1);
                b0 = Bs[1][nn][kk * 8 + tq]; b1 = Bs[1][nn][kk * 8 + tq + 4];
                mma8(accz[nb], a0, a1, a2, a3, b0, b1);
                b0 = Bs[2][nn][kk * 8 + tq]; b1 = Bs[2][nn][kk * 8 + tq + 4];
                mma8(accn[nb], a0, a1, a2, a3, b0, b1);
            }
        }
        __syncthreads();
    }

    // Gate epilogue
    #pragma unroll
    for (int nb = 0; nb < 4; nb++) {
        #pragma unroll
        for (int half = 0; half < 2; half++) {
            int brow = m0 + mo + gq + half * 8;
            #pragma unroll
            for (int cc = 0; cc < 2; cc++) {
                int j = n0 + no + nb * 8 + 2 * tq + cc;
                int idx = half * 2 + cc;
                float r_ = sigm(accr[nb][idx] + bih[j] + bhh[j]);
                float z_ = sigm(accz[nb][idx] + bih[Hn + j] + bhh[Hn + j]);
                float n_ = tanh_fast(accnx[nb][idx] + bih[2 * Hn + j]
                                     + r_ * (accnh[nb][idx] + bhh[2 * Hn + j]));
                float ho = hold[(size_t)brow * Hn + j];
                hnew[(size_t)brow * Hn + j] = (1.f - z_) * n_ + z_ * ho;
            }
        }
    }
}

// ---------------- LayerNorm of h_last -----------------------------------------
__global__ void __launch_bounds__(256) hln_kernel(const float* __restrict__ g,
                                                  const float* __restrict__ be) {
    int row = blockIdx.x * 8 + (threadIdx.x >> 5);
    int lane = threadIdx.x & 31;
    const float* hp = d_hB + (size_t)row * Hn;
    float4 v[4];
    float s = 0.f, sq = 0.f;
    #pragma unroll
    for (int i = 0; i < 4; i++) {
        v[i] = *(const float4*)(hp + lane * 4 + i * 128);
        s += v[i].x + v[i].y + v[i].z + v[i].w;
        sq += v[i].x * v[i].x + v[i].y * v[i].y + v[i].z * v[i].z + v[i].w * v[i].w;
    }
    #pragma unroll
    for (int o = 16; o; o >>= 1) {
        s += __shfl_xor_sync(~0u, s, o);
        sq += __shfl_xor_sync(~0u, sq, o);
    }
    float m = s / 512.f, var = sq / 512.f - m * m;
    float rs = rsqrtf(var + 1e-5f);
    float* op = d_hln + (size_t)row * Hn;
    #pragma unroll
    for (int i = 0; i < 4; i++) {
        int c = lane * 4 + i * 128;
        float4 o4;
        o4.x = (v[i].x - m) * rs * g[c] + be[c];
        o4.y = (v[i].y - m) * rs * g[c + 1] + be[c + 1];
        o4.z = (v[i].z - m) * rs * g[c + 2] + be[c + 2];
        o4.w = (v[i].w - m) * rs * g[c + 3] + be[c + 3];
        *(float4*)(op + c) = o4;
    }
}

// ---------------- fc: sigmoid(hln @ fc_W^T + fc_b) ----------------------------
__global__ void __launch_bounds__(256) fc_kernel(const float* __restrict__ W,
                                                 const float* __restrict__ bias,
                                                 float* __restrict__ out) {
    __shared__ uint32_t As[64][68];
    __shared__ uint32_t Bs[64][68];
    const int tid = threadIdx.x;
    const int warp = tid >> 5, lane = tid & 31;
    const int gq = lane >> 2, tq = lane & 3;
    const int n0 = blockIdx.x * 64, m0 = blockIdx.y * 64;
    const int mo = (warp & 3) * 16, no = (warp >> 2) * 32;
    float acc[4][4] = {};

    for (int it = 0; it < 8; ++it) {
        int k0 = it * 64;
        #pragma unroll
        for (int j = 0; j < 4; j++) {
            int lin = tid + j * 256;
            int r = lin >> 4, cc = lin & 15;
            float4 va = *(const float4*)(d_hln + (size_t)(m0 + r) * Hn + k0 + cc * 4);
            st_tf32(&As[r][cc * 4], va);
            float4 vb = *(const float4*)(W + (size_t)(n0 + r) * Hn + k0 + cc * 4);
            st_tf32(&Bs[r][cc * 4], vb);
        }
        __syncthreads();
        #pragma unroll
        for (int kk = 0; kk < 8; kk++) {
            uint32_t a0 = As[mo + gq][kk * 8 + tq];
            uint32_t a1 = As[mo + gq + 8][kk * 8 + tq];
            uint32_t a2 = As[mo + gq][kk * 8 + tq + 4];
            uint32_t a3 = As[mo + gq + 8][kk * 8 + tq + 4];
            #pragma unroll
            for (int nb = 0; nb < 4; nb++) {
                uint32_t b0 = Bs[no + nb * 8 + gq][kk * 8 + tq];
                uint32_t b1 = Bs[no + nb * 8 + gq][kk * 8 + tq + 4];
                mma8(acc[nb], a0, a1, a2, a3, b0, b1);
            }
        }
        __syncthreads();
    }

    #pragma unroll
    for (int nb = 0; nb < 4; nb++) {
        #pragma unroll
        for (int half = 0; half < 2; half++) {
            int row = m0 + mo + gq + half * 8;
            #pragma unroll
            for (int cc = 0; cc < 2; cc++) {
                int j = n0 + no + nb * 8 + 2 * tq + cc;
                out[(size_t)row * On + j] = sigm(acc[nb][half * 2 + cc] + bias[j]);
            }
        }
    }
}

// ---------------- launch ------------------------------------------------------
extern "C" void kernel_launch(void* const* d_in, const int* in_sizes, int n_in,
                              void* d_out, int out_size) {
    const float* msg      = (const float*)d_in[0];
    const float* emb_W    = (const float*)d_in[1];
    const float* emb_b    = (const float*)d_in[2];
    const float* init_emb = (const float*)d_in[3];
    const float* eln_g    = (const float*)d_in[4];
    const float* eln_b    = (const float*)d_in[5];
    const float* Wih      = (const float*)d_in[6];
    const float* Whh      = (const float*)d_in[7];
    const float* bih      = (const float*)d_in[8];
    const float* bhh      = (const float*)d_in[9];
    const float* gln_g    = (const float*)d_in[10];
    const float* gln_b    = (const float*)d_in[11];
    const float* fc_W     = (const float*)d_in[12];
    const float* fc_b     = (const float*)d_in[13];
    float* out = (float*)d_out;

    ln0_kernel<<<1, 32>>>(init_emb, eln_g, eln_b);
    zero_kernel<<<(Bn * Hn / 4) / 256, 256>>>();
    embed_kernel<<<(Bn * 4) / 32, 64>>>(msg, emb_W, emb_b, eln_g, eln_b);
    for (int t = 0; t < Tn; t++)
        gru_kernel<<<dim3(Hn / 64, Bn / 64), 256>>>(Wih, Whh, bih, bhh, t);
    hln_kernel<<<Bn / 8, 256>>>(gln_g, gln_b);
    fc_kernel<<<dim3(On / 64, Bn / 64), 256>>>(fc_W, fc_b, out);
}

// round 2
// speedup vs baseline: 1.1312x; 1.1312x over previous
#include <cuda_runtime.h>
#include <cstdint>

#define Bn 4096
#define Tn 5
#define Vn 8192
#define En 32
#define Hn 512
#define On 1024

// ---------------- scratch (device globals) -----------------------------------
__device__ __align__(16) uint32_t d_Xp[Tn * Bn * En];  // packed tf32 GRU inputs (slot t)
__device__ __align__(16) uint32_t d_X0p[En];           // packed LN(init_emb)
__device__ __align__(16) float    d_hA[Bn * Hn];
__device__ __align__(16) float    d_hB[Bn * Hn];
__device__ __align__(16) uint32_t d_hpA[Bn * Hn];      // packed tf32 h
__device__ __align__(16) uint32_t d_hpB[Bn * Hn];
__device__ __align__(16) uint32_t d_hlnp[Bn * Hn];     // packed tf32 LN(h)
// packed weights (tf32, k-pair permuted, tile-ordered)
__device__ __align__(16) uint32_t d_pWhh[16 * 3 * Hn * 32];
__device__ __align__(16) uint32_t d_pWih[3 * Hn * En];
__device__ __align__(16) uint32_t d_pEmb[(Vn / 32) * En * 32];
__device__ __align__(16) uint32_t d_pFc[(Hn / 32) * On * 32];

// ---------------- helpers -----------------------------------------------------
__device__ __forceinline__ uint32_t f2tf(float x) {
    uint32_t r; asm volatile("cvt.rna.tf32.f32 %0, %1;" : "=r"(r) : "f"(x)); return r;
}
__device__ __forceinline__ void mma8(float c[4], uint32_t a0, uint32_t a1, uint32_t a2,
                                     uint32_t a3, uint32_t b0, uint32_t b1) {
    asm volatile(
        "mma.sync.aligned.m16n8k8.row.col.f32.tf32.tf32.f32 "
        "{%0,%1,%2,%3}, {%4,%5,%6,%7}, {%8,%9}, {%0,%1,%2,%3};"
        : "+f"(c[0]), "+f"(c[1]), "+f"(c[2]), "+f"(c[3])
        : "r"(a0), "r"(a1), "r"(a2), "r"(a3), "r"(b0), "r"(b1));
}
__device__ __forceinline__ float sigm(float x) { return 1.f / (1.f + __expf(-x)); }
__device__ __forceinline__ float tanh_fast(float x) { return 1.f - 2.f / (1.f + __expf(2.f * x)); }
__device__ __forceinline__ void cp16(uint32_t dst, const void* src) {
    asm volatile("cp.async.cg.shared.global [%0], [%1], 16;" :: "r"(dst), "l"(src));
}
__device__ __forceinline__ void cp_commit() { asm volatile("cp.async.commit_group;"); }
template <int N> __device__ __forceinline__ void cp_wait() {
    asm volatile("cp.async.wait_group %0;" :: "n"(N));
}
// k-pair permutation: within each 8-k chunk, value k sits at p = (k&3)*2 + (k>>2)
__device__ __forceinline__ int wofk(int k) { return (k >> 3) * 8 + (k & 3) * 2 + ((k >> 2) & 1); }
__device__ __forceinline__ int kofw(int w) { return (w >> 3) * 8 + ((w & 7) >> 1) + ((w & 1) << 2); }

// ---------------- weight pack kernels -----------------------------------------
__global__ void pack_whh(const float* __restrict__ W) {
    int idx = blockIdx.x * 256 + threadIdx.x;          // 16*3*512*32
    int w = idx & 31; int t2 = idx >> 5;
    int n = t2 & 511; int u = t2 >> 9;
    int gt = u % 3, it = u / 3;
    int k = it * 32 + kofw(w);
    d_pWhh[idx] = f2tf(W[(size_t)(gt * Hn + n) * Hn + k]);
}
__global__ void pack_wih(const float* __restrict__ W) {
    int idx = blockIdx.x * 256 + threadIdx.x;          // 3*512*32
    int w = idx & 31; int n = (idx >> 5) & 511; int gt = idx >> 14;
    d_pWih[idx] = f2tf(W[(size_t)(gt * Hn + n) * En + kofw(w)]);
}
__global__ void pack_emb(const float* __restrict__ W) {
    int idx = blockIdx.x * 256 + threadIdx.x;          // 256*32*32
    int w = idx & 31; int n = (idx >> 5) & 31; int it = idx >> 10;
    int k = it * 32 + kofw(w);
    d_pEmb[idx] = f2tf(W[(size_t)n * Vn + k]);
}
__global__ void pack_fcw(const float* __restrict__ W) {
    int idx = blockIdx.x * 256 + threadIdx.x;          // 16*1024*32
    int w = idx & 31; int n = (idx >> 5) & 1023; int it = idx >> 15;
    int k = it * 32 + kofw(w);
    d_pFc[idx] = f2tf(W[(size_t)n * Hn + k]);
}

// ---------------- tiny kernels -------------------------------------------------
__global__ void ln0_kernel(const float* __restrict__ init_emb,
                           const float* __restrict__ g, const float* __restrict__ b) {
    int l = threadIdx.x;
    float v = init_emb[l];
    float s = v, sq = v * v;
    #pragma unroll
    for (int o = 16; o; o >>= 1) {
        s += __shfl_xor_sync(~0u, s, o);
        sq += __shfl_xor_sync(~0u, sq, o);
    }
    float m = s / 32.f, var = sq / 32.f - m * m;
    float rs = rsqrtf(var + 1e-5f);
    d_X0p[wofk(l)] = f2tf((v - m) * rs * g[l] + b[l]);
}
__global__ void zero2_kernel() {
    int i = blockIdx.x * blockDim.x + threadIdx.x;
    const int N = Bn * Hn / 4;
    float4 z = make_float4(0.f, 0.f, 0.f, 0.f);
    if (i < N) ((float4*)d_hA)[i] = z;
    else       ((float4*)d_hpA)[i - N] = z;
}

// ---------------- embedding GEMM + LN ------------------------------------------
// M=16384 (m=b*4+t, t<4), N=32, K=8192. BM=128, BK=32, 256 thr, cp.async 2-stage.
__global__ void __launch_bounds__(256, 1) embed_kernel(
    const float* __restrict__ msg, const float* __restrict__ eb,
    const float* __restrict__ gw, const float* __restrict__ bw) {
    extern __shared__ uint32_t sm[];
    const int tid = threadIdx.x, warp = tid >> 5, lane = tid & 31;
    const int gq = lane >> 2, tq = lane & 3;
    const int m0 = blockIdx.x * 128;
    const uint32_t smb = (uint32_t)__cvta_generic_to_shared(sm);

    auto prefetch = [&](int it) {
        int s = it & 1, k0 = it * 32;
        uint32_t ab = smb + s * 5120 * 4;
        uint32_t bb = ab + 4096 * 4;
        #pragma unroll
        for (int j = 0; j < 4; j++) {
            int id = tid + j * 256; int row = id >> 3, cc = id & 7;
            int m = m0 + row; int b = m >> 2, tt = m & 3;
            uint32_t dst = ab + row * 128 + (((cc * 4) ^ ((row & 3) * 8)) * 4);
            cp16(dst, msg + ((size_t)b * Tn + tt) * Vn + k0 + cc * 4);
        }
        { // B: 32 rows x 8 chunks = 256
            int row = tid >> 3, cc = tid & 7;
            uint32_t dst = bb + row * 128 + (((cc * 4) ^ ((row & 3) * 8)) * 4);
            cp16(dst, d_pEmb + ((size_t)it * En + row) * 32 + cc * 4);
        }
        cp_commit();
    };

    float acc[4][4] = {};
    prefetch(0);
    for (int it = 0; it < Vn / 32; ++it) {
        if (it + 1 < Vn / 32) { prefetch(it + 1); cp_wait<1>(); }
        else cp_wait<0>();
        __syncthreads();
        const uint32_t* A = sm + (it & 1) * 5120;
        const uint32_t* B = A + 4096;
        #pragma unroll
        for (int kk = 0; kk < 4; ++kk) {
            int r0 = warp * 16 + gq, r1 = r0 + 8;
            uint32_t a0 = A[r0 * 32 + ((kk * 8 + tq)     ^ ((r0 & 3) * 8))];
            uint32_t a2 = A[r0 * 32 + ((kk * 8 + tq + 4) ^ ((r0 & 3) * 8))];
            uint32_t a1 = A[r1 * 32 + ((kk * 8 + tq)     ^ ((r1 & 3) * 8))];
            uint32_t a3 = A[r1 * 32 + ((kk * 8 + tq + 4) ^ ((r1 & 3) * 8))];
            a0 = f2tf(__uint_as_float(a0)); a1 = f2tf(__uint_as_float(a1));
            a2 = f2tf(__uint_as_float(a2)); a3 = f2tf(__uint_as_float(a3));
            #pragma unroll
            for (int nb = 0; nb < 4; ++nb) {
                int br = nb * 8 + gq;
                uint2 bp = *(const uint2*)&B[br * 32 + ((kk * 8 + tq * 2) ^ ((br & 3) * 8))];
                mma8(acc[nb], a0, a1, a2, a3, bp.x, bp.y);
            }
        }
        __syncthreads();
    }

    // LN epilogue: quad (lanes w/ same gq) holds one full 32-wide row
    float v0[8], v1[8];
    int col[8];
    #pragma unroll
    for (int nb = 0; nb < 4; nb++) {
        col[nb * 2] = nb * 8 + 2 * tq;
        col[nb * 2 + 1] = nb * 8 + 2 * tq + 1;
        float e0 = eb[col[nb * 2]], e1 = eb[col[nb * 2 + 1]];
        v0[nb * 2] = acc[nb][0] + e0; v0[nb * 2 + 1] = acc[nb][1] + e1;
        v1[nb * 2] = acc[nb][2] + e0; v1[nb * 2 + 1] = acc[nb][3] + e1;
    }
    auto LNROW = [&](float* v, int mrow) {
        float s = 0.f, sq = 0.f;
        #pragma unroll
        for (int i = 0; i < 8; i++) { s += v[i]; sq += v[i] * v[i]; }
        s += __shfl_xor_sync(~0u, s, 1); sq += __shfl_xor_sync(~0u, sq, 1);
        s += __shfl_xor_sync(~0u, s, 2); sq += __shfl_xor_sync(~0u, sq, 2);
        float m = s / 32.f, var = sq / 32.f - m * m;
        float rs = rsqrtf(var + 1e-5f);
        int bb2 = mrow >> 2, tt = mrow & 3;
        uint32_t* xp = d_Xp + ((size_t)(tt + 1) * Bn + bb2) * En;
        #pragma unroll
        for (int i = 0; i < 8; i++)
            xp[wofk(col[i])] = f2tf((v[i] - m) * rs * gw[col[i]] + bw[col[i]]);
    };
    LNROW(v0, m0 + warp * 16 + gq);
    LNROW(v1, m0 + warp * 16 + gq + 8);
}

// ---------------- GRU step ------------------------------------------------------
// BM=128, BN=64 (x3 gates), BK=32, 17 K-iters (iter0 = x slice). 256 threads.
__global__ void __launch_bounds__(256, 1) gru_kernel(
    const float* __restrict__ bih, const float* __restrict__ bhh, int t) {
    extern __shared__ uint32_t sm[];
    const int tid = threadIdx.x, warp = tid >> 5, lane = tid & 31;
    const int gq = lane >> 2, tq = lane & 3;
    const int n0 = blockIdx.x * 64, m0 = blockIdx.y * 128;
    const int mo = (warp & 3) * 32, no = (warp >> 2) * 32;
    const float*    hold  = (t & 1) ? d_hB  : d_hA;
    float*          hnew  = (t & 1) ? d_hA  : d_hB;
    const uint32_t* hpold = (t & 1) ? d_hpB : d_hpA;
    uint32_t*       hpnew = (t & 1) ? d_hpA : d_hpB;
    const uint32_t smb = (uint32_t)__cvta_generic_to_shared(sm);

    auto prefetch = [&](int it) {
        int s = it & 1;
        uint32_t ab = smb + s * 10240 * 4;
        uint32_t bb = ab + 4096 * 4;
        #pragma unroll
        for (int j = 0; j < 4; j++) {           // A: 128 rows x 8 chunks
            int id = tid + j * 256; int row = id >> 3, cc = id & 7;
            uint32_t dst = ab + row * 128 + (((cc * 4) ^ ((row & 3) * 8)) * 4);
            const uint32_t* src;
            if (it == 0)
                src = (t == 0) ? (d_X0p + cc * 4)
                               : (d_Xp + ((size_t)t * Bn + m0 + row) * En + cc * 4);
            else
                src = hpold + (size_t)(m0 + row) * Hn + (it - 1) * 32 + cc * 4;
            cp16(dst, src);
        }
        #pragma unroll
        for (int j = 0; j < 6; j++) {           // B: 3 x 64 rows x 8 chunks
            int id = tid + j * 256; int gt = id >> 9, rem = id & 511;
            int row = rem >> 3, cc = rem & 7;
            int brow = gt * 64 + row;
            uint32_t dst = bb + brow * 128 + (((cc * 4) ^ ((brow & 3) * 8)) * 4);
            const uint32_t* src = (it == 0)
                ? d_pWih + ((size_t)gt * Hn + n0 + row) * 32 + cc * 4
                : d_pWhh + (((size_t)(it - 1) * 3 + gt) * Hn + n0 + row) * 32 + cc * 4;
            cp16(dst, src);
        }
        cp_commit();
    };

    float accr[2][4][4] = {}, accz[2][4][4] = {}, accnh[2][4][4] = {}, accnx[2][4][4] = {};

    prefetch(0);
    for (int it = 0; it < 17; ++it) {
        if (it + 1 < 17) { prefetch(it + 1); cp_wait<1>(); }
        else cp_wait<0>();
        __syncthreads();
        const uint32_t* A = sm + (it & 1) * 10240;
        const uint32_t* B = A + 4096;

        auto tile = [&](float (&an)[2][4][4]) {
            #pragma unroll
            for (int kk = 0; kk < 4; ++kk) {
                uint32_t a[2][4];
                #pragma unroll
                for (int mf = 0; mf < 2; ++mf) {
                    int r0 = mo + mf * 16 + gq, r1 = r0 + 8;
                    uint2 p0 = *(const uint2*)&A[r0 * 32 + ((kk * 8 + tq * 2) ^ ((r0 & 3) * 8))];
                    uint2 p1 = *(const uint2*)&A[r1 * 32 + ((kk * 8 + tq * 2) ^ ((r1 & 3) * 8))];
                    a[mf][0] = p0.x; a[mf][2] = p0.y; a[mf][1] = p1.x; a[mf][3] = p1.y;
                }
                #pragma unroll
                for (int nb = 0; nb < 4; ++nb) {
                    int br0 = 0 * 64 + no + nb * 8 + gq;
                    int br1 = 1 * 64 + no + nb * 8 + gq;
                    int br2 = 2 * 64 + no + nb * 8 + gq;
                    uint2 b0 = *(const uint2*)&B[br0 * 32 + ((kk * 8 + tq * 2) ^ ((br0 & 3) * 8))];
                    uint2 b1 = *(const uint2*)&B[br1 * 32 + ((kk * 8 + tq * 2) ^ ((br1 & 3) * 8))];
                    uint2 b2 = *(const uint2*)&B[br2 * 32 + ((kk * 8 + tq * 2) ^ ((br2 & 3) * 8))];
                    #pragma unroll
                    for (int mf = 0; mf < 2; ++mf) {
                        mma8(accr[mf][nb], a[mf][0], a[mf][1], a[mf][2], a[mf][3], b0.x, b0.y);
                        mma8(accz[mf][nb], a[mf][0], a[mf][1], a[mf][2], a[mf][3], b1.x, b1.y);
                        mma8(an  [mf][nb], a[mf][0], a[mf][1], a[mf][2], a[mf][3], b2.x, b2.y);
                    }
                }
            }
        };
        if (it == 0) tile(accnx); else tile(accnh);
        __syncthreads();
    }

    // gate epilogue
    #pragma unroll
    for (int mf = 0; mf < 2; ++mf)
    #pragma unroll
    for (int nb = 0; nb < 4; ++nb)
    #pragma unroll
    for (int idx = 0; idx < 4; ++idx) {
        int brow = m0 + mo + mf * 16 + gq + (idx >> 1) * 8;
        int j = n0 + no + nb * 8 + 2 * tq + (idx & 1);
        float r_ = sigm(accr[mf][nb][idx] + bih[j] + bhh[j]);
        float z_ = sigm(accz[mf][nb][idx] + bih[Hn + j] + bhh[Hn + j]);
        float n_ = tanh_fast(accnx[mf][nb][idx] + bih[2 * Hn + j]
                             + r_ * (accnh[mf][nb][idx] + bhh[2 * Hn + j]));
        float ho = hold[(size_t)brow * Hn + j];
        float hv = (1.f - z_) * n_ + z_ * ho;
        hnew[(size_t)brow * Hn + j] = hv;
        hpnew[(size_t)brow * Hn + (j >> 3) * 8 + (j & 3) * 2 + ((j >> 2) & 1)] = f2tf(hv);
    }
}

// ---------------- LN(h_last) → packed tf32 --------------------------------------
__global__ void __launch_bounds__(256) hln_kernel(const float* __restrict__ g,
                                                  const float* __restrict__ be) {
    int row = blockIdx.x * 8 + (threadIdx.x >> 5);
    int lane = threadIdx.x & 31;
    const float* hp = d_hB + (size_t)row * Hn;
    float4 v[4];
    float s = 0.f, sq = 0.f;
    #pragma unroll
    for (int i = 0; i < 4; i++) {
        v[i] = *(const float4*)(hp + lane * 4 + i * 128);
        s += v[i].x + v[i].y + v[i].z + v[i].w;
        sq += v[i].x * v[i].x + v[i].y * v[i].y + v[i].z * v[i].z + v[i].w * v[i].w;
    }
    #pragma unroll
    for (int o = 16; o; o >>= 1) {
        s += __shfl_xor_sync(~0u, s, o);
        sq += __shfl_xor_sync(~0u, sq, o);
    }
    float m = s / 512.f, var = sq / 512.f - m * m;
    float rs = rsqrtf(var + 1e-5f);
    uint32_t* op = d_hlnp + (size_t)row * Hn;
    #pragma unroll
    for (int i = 0; i < 4; i++) {
        int c = lane * 4 + i * 128;
        float vv[4] = {v[i].x, v[i].y, v[i].z, v[i].w};
        #pragma unroll
        for (int q = 0; q < 4; q++) {
            int k = c + q;
            op[(k >> 3) * 8 + (k & 3) * 2 + ((k >> 2) & 1)] =
                f2tf((vv[q] - m) * rs * g[k] + be[k]);
        }
    }
}

// ---------------- fc: sigmoid(hln @ fc_W^T + b) ---------------------------------
// BM=128, BN=64, BK=32, 16 iters, 256 threads, cp.async 2-stage.
__global__ void __launch_bounds__(256, 1) fc_kernel(const float* __restrict__ bias,
                                                    float* __restrict__ out) {
    extern __shared__ uint32_t sm[];
    const int tid = threadIdx.x, warp = tid >> 5, lane = tid & 31;
    const int gq = lane >> 2, tq = lane & 3;
    const int n0 = blockIdx.x * 64, m0 = blockIdx.y * 128;
    const int mo = (warp & 3) * 32, no = (warp >> 2) * 32;
    const uint32_t smb = (uint32_t)__cvta_generic_to_shared(sm);

    auto prefetch = [&](int it) {
        int s = it & 1;
        uint32_t ab = smb + s * 6144 * 4;
        uint32_t bb = ab + 4096 * 4;
        #pragma unroll
        for (int j = 0; j < 4; j++) {          // A: 128x8
            int id = tid + j * 256; int row = id >> 3, cc = id & 7;
            uint32_t dst = ab + row * 128 + (((cc * 4) ^ ((row & 3) * 8)) * 4);
            cp16(dst, d_hlnp + (size_t)(m0 + row) * Hn + it * 32 + cc * 4);
        }
        #pragma unroll
        for (int j = 0; j < 2; j++) {          // B: 64x8
            int id = tid + j * 256; int row = id >> 3, cc = id & 7;
            uint32_t dst = bb + row * 128 + (((cc * 4) ^ ((row & 3) * 8)) * 4);
            cp16(dst, d_pFc + ((size_t)it * On + n0 + row) * 32 + cc * 4);
        }
        cp_commit();
    };

    float acc[2][4][4] = {};
    prefetch(0);
    for (int it = 0; it < 16; ++it) {
        if (it + 1 < 16) { prefetch(it + 1); cp_wait<1>(); }
        else cp_wait<0>();
        __syncthreads();
        const uint32_t* A = sm + (it & 1) * 6144;
        const uint32_t* B = A + 4096;
        #pragma unroll
        for (int kk = 0; kk < 4; ++kk) {
            uint32_t a[2][4];
            #pragma unroll
            for (int mf = 0; mf < 2; ++mf) {
                int r0 = mo + mf * 16 + gq, r1 = r0 + 8;
                uint2 p0 = *(const uint2*)&A[r0 * 32 + ((kk * 8 + tq * 2) ^ ((r0 & 3) * 8))];
                uint2 p1 = *(const uint2*)&A[r1 * 32 + ((kk * 8 + tq * 2) ^ ((r1 & 3) * 8))];
                a[mf][0] = p0.x; a[mf][2] = p0.y; a[mf][1] = p1.x; a[mf][3] = p1.y;
            }
            #pragma unroll
            for (int nb = 0; nb < 4; ++nb) {
                int br = no + nb * 8 + gq;
                uint2 bp = *(const uint2*)&B[br * 32 + ((kk * 8 + tq * 2) ^ ((br & 3) * 8))];
                #pragma unroll
                for (int mf = 0; mf < 2; ++mf)
                    mma8(acc[mf][nb], a[mf][0], a[mf][1], a[mf][2], a[mf][3], bp.x, bp.y);
            }
        }
        __syncthreads();
    }
    #pragma unroll
    for (int mf = 0; mf < 2; ++mf)
    #pragma unroll
    for (int nb = 0; nb < 4; ++nb)
    #pragma unroll
    for (int idx = 0; idx < 4; ++idx) {
        int row = m0 + mo + mf * 16 + gq + (idx >> 1) * 8;
        int j = n0 + no + nb * 8 + 2 * tq + (idx & 1);
        out[(size_t)row * On + j] = sigm(acc[mf][nb][idx] + bias[j]);
    }
}

// ---------------- launch ---------------------------------------------------------
extern "C" void kernel_launch(void* const* d_in, const int* in_sizes, int n_in,
                              void* d_out, int out_size) {
    const float* msg      = (const float*)d_in[0];
    const float* emb_W    = (const float*)d_in[1];
    const float* emb_b    = (const float*)d_in[2];
    const float* init_emb = (const float*)d_in[3];
    const float* eln_g    = (const float*)d_in[4];
    const float* eln_b    = (const float*)d_in[5];
    const float* Wih      = (const float*)d_in[6];
    const float* Whh      = (const float*)d_in[7];
    const float* bih      = (const float*)d_in[8];
    const float* bhh      = (const float*)d_in[9];
    const float* gln_g    = (const float*)d_in[10];
    const float* gln_b    = (const float*)d_in[11];
    const float* fc_W     = (const float*)d_in[12];
    const float* fc_b     = (const float*)d_in[13];
    float* out = (float*)d_out;

    static bool attr_done = false;
    cudaFuncSetAttribute(embed_kernel, cudaFuncAttributeMaxDynamicSharedMemorySize, 40960);
    cudaFuncSetAttribute(gru_kernel,   cudaFuncAttributeMaxDynamicSharedMemorySize, 81920);
    cudaFuncSetAttribute(fc_kernel,    cudaFuncAttributeMaxDynamicSharedMemorySize, 49152);
    (void)attr_done;

    pack_whh<<<(16 * 3 * Hn * 32) / 256, 256>>>(Whh);
    pack_wih<<<(3 * Hn * 32) / 256, 256>>>(Wih);
    pack_emb<<<((Vn / 32) * En * 32) / 256, 256>>>(emb_W);
    pack_fcw<<<((Hn / 32) * On * 32) / 256, 256>>>(fc_W);
    ln0_kernel<<<1, 32>>>(init_emb, eln_g, eln_b);
    zero2_kernel<<<(2 * Bn * Hn / 4) / 256, 256>>>();
    embed_kernel<<<(Bn * 4) / 128, 256, 40960>>>(msg, emb_b, eln_g, eln_b);
    for (int t = 0; t < Tn; t++)
        gru_kernel<<<dim3(Hn / 64, Bn / 128), 256, 81920>>>(bih, bhh, t);
    hln_kernel<<<Bn / 8, 256>>>(gln_g, gln_b);
    fc_kernel<<<dim3(On / 64, Bn / 128), 256, 49152>>>(fc_b, out);
}